// round 1
// baseline (speedup 1.0000x reference)
#include <cuda_runtime.h>
#include <math.h>

#define T_SEQ 8192
#define HID   1024
#define GDIM  2048          // 2*H
#define NCTA  128
#define RECT  256           // threads per recurrence CTA (8 warps = 8 h-outputs)

// ---------------- scratch (static __device__, no allocation) ----------------
__device__ float g_gi[T_SEQ * GDIM];     // 64 MB  input projection for current layer
__device__ float g_Xa[T_SEQ * HID];      // 32 MB  layer output ping
__device__ float g_Xb[T_SEQ * HID];      // 32 MB  layer output pong
__device__ float g_h[2][HID];            // double-buffered hidden state
__device__ volatile int g_flags[NCTA];   // per-CTA progress flags

// ---------------- per-layer init: zero flags, load h0 ----------------
__global__ void init_phase(const float* __restrict__ h0, int layer) {
    int tid = blockIdx.x * blockDim.x + threadIdx.x;
    if (tid < NCTA) g_flags[tid] = 0;
    if (tid < HID)  g_h[0][tid] = h0[layer * HID + tid];
}

// ---------------- C[M,N] = A[M,K] @ W[N,K]^T + bias[N] ----------------
// BM=BN=128, BK=8, 256 threads, 8x8 register tile per thread.
__global__ __launch_bounds__(256, 2)
void gemm_bias_nt(const float* __restrict__ A, const float* __restrict__ W,
                  const float* __restrict__ bias, float* __restrict__ C,
                  int M, int N, int K) {
    __shared__ float As[8][128];
    __shared__ float Bs[8][128];
    const int tid  = threadIdx.x;
    const int bm   = blockIdx.y * 128;
    const int bn   = blockIdx.x * 128;
    const int lrow = tid >> 1;           // 0..127
    const int lcol = (tid & 1) << 2;     // 0 or 4
    const int ty   = tid >> 4;           // 0..15
    const int tx   = tid & 15;           // 0..15

    float acc[8][8];
#pragma unroll
    for (int i = 0; i < 8; ++i)
#pragma unroll
        for (int j = 0; j < 8; ++j) acc[i][j] = 0.f;

    const float* Aptr = A + (size_t)(bm + lrow) * K + lcol;
    const float* Wptr = W + (size_t)(bn + lrow) * K + lcol;

    for (int k0 = 0; k0 < K; k0 += 8) {
        float4 av = *(const float4*)(Aptr + k0);
        float4 wv = *(const float4*)(Wptr + k0);
        As[lcol + 0][lrow] = av.x; As[lcol + 1][lrow] = av.y;
        As[lcol + 2][lrow] = av.z; As[lcol + 3][lrow] = av.w;
        Bs[lcol + 0][lrow] = wv.x; Bs[lcol + 1][lrow] = wv.y;
        Bs[lcol + 2][lrow] = wv.z; Bs[lcol + 3][lrow] = wv.w;
        __syncthreads();
#pragma unroll
        for (int k = 0; k < 8; ++k) {
            float4 a0 = *(const float4*)&As[k][ty * 8];
            float4 a1 = *(const float4*)&As[k][ty * 8 + 4];
            float4 b0 = *(const float4*)&Bs[k][tx * 8];
            float4 b1 = *(const float4*)&Bs[k][tx * 8 + 4];
            float ar[8] = {a0.x, a0.y, a0.z, a0.w, a1.x, a1.y, a1.z, a1.w};
            float br[8] = {b0.x, b0.y, b0.z, b0.w, b1.x, b1.y, b1.z, b1.w};
#pragma unroll
            for (int i = 0; i < 8; ++i)
#pragma unroll
                for (int j = 0; j < 8; ++j) acc[i][j] += ar[i] * br[j];
        }
        __syncthreads();
    }

#pragma unroll
    for (int i = 0; i < 8; ++i) {
        int row = bm + ty * 8 + i;
#pragma unroll
        for (int j = 0; j < 8; j += 4) {
            float4 v;
            int col = bn + tx * 8 + j;
            v.x = acc[i][j + 0] + bias[col + 0];
            v.y = acc[i][j + 1] + bias[col + 1];
            v.z = acc[i][j + 2] + bias[col + 2];
            v.w = acc[i][j + 3] + bias[col + 3];
            *(float4*)&C[(size_t)row * N + col] = v;
        }
    }
}

// ---------------- persistent MGU recurrence for one layer ----------------
// 128 CTAs x 256 threads. CTA c, warp w owns h-index j = c*8+w:
// rows j (forget) and j+1024 (candidate) of w_hh live in registers.
__global__ __launch_bounds__(RECT, 1)
void mgu_recur(const float* __restrict__ w_hh, const float* __restrict__ b_hh,
               const float* __restrict__ gi, float* __restrict__ X) {
    __shared__ float4 h_s[HID / 4];   // full h, 4 KB

    const int cta  = blockIdx.x;
    const int tid  = threadIdx.x;
    const int warp = tid >> 5;
    const int lane = tid & 31;
    const int j    = cta * 8 + warp;     // h output index / forget row
    const int rn   = j + HID;            // candidate row

    // preload this warp's two weight rows into registers (64 floats/lane)
    float4 wf[8], wn[8];
#pragma unroll
    for (int i = 0; i < 8; ++i) {
        int col = 4 * (i * 32 + lane);
        wf[i] = *(const float4*)&w_hh[(size_t)j  * HID + col];
        wn[i] = *(const float4*)&w_hh[(size_t)rn * HID + col];
    }
    const float bf  = b_hh[j];
    const float bnn = b_hh[rn];

    for (int t = 0; t < T_SEQ; ++t) {
        // prefetch gi for this step (no dependence on the barrier)
        float gif = 0.f, gin = 0.f;
        if (lane == 0) {
            gif = __ldcg(&gi[(size_t)t * GDIM + j]);
            gin = __ldcg(&gi[(size_t)t * GDIM + HID + j]);
        }

        // distributed flag barrier: wait until every CTA finished step t-1
        if (warp == 0) {
            for (;;) {
                int a = g_flags[lane];
                int b = g_flags[lane + 32];
                int c = g_flags[lane + 64];
                int d = g_flags[lane + 96];
                int m = min(min(a, b), min(c, d));
                if (__all_sync(0xffffffffu, m >= t)) break;
            }
        }
        __syncthreads();

        // stage h(t-1) into shared
        const float4* hsrc = (const float4*)g_h[t & 1];
        h_s[tid] = __ldcg(&hsrc[tid]);
        __syncthreads();

        // two 1024-length dot products per warp, weights from registers
        float accf = 0.f, accn = 0.f;
#pragma unroll
        for (int i = 0; i < 8; ++i) {
            float4 h4 = h_s[i * 32 + lane];
            accf += wf[i].x * h4.x + wf[i].y * h4.y + wf[i].z * h4.z + wf[i].w * h4.w;
            accn += wn[i].x * h4.x + wn[i].y * h4.y + wn[i].z * h4.z + wn[i].w * h4.w;
        }
#pragma unroll
        for (int off = 16; off; off >>= 1) {
            accf += __shfl_down_sync(0xffffffffu, accf, off);
            accn += __shfl_down_sync(0xffffffffu, accn, off);
        }

        if (lane == 0) {
            float f     = 1.f / (1.f + expf(-(gif + accf + bf)));
            float n     = tanhf(gin + f * (accn + bnn));
            float hprev = ((const float*)h_s)[j];
            float hy    = n + (1.f - f) * (hprev - n);
            g_h[(t + 1) & 1][j]     = hy;
            X[(size_t)t * HID + j]  = hy;
            __threadfence();
        }
        __syncthreads();
        if (tid == 0) g_flags[cta] = t + 1;   // volatile store (publish step t)
    }
}

// ---------------- final projection: out[t] = X[t] . w_out + b_out ----------------
__global__ void out_proj(const float* __restrict__ X, const float* __restrict__ w_out,
                         const float* __restrict__ b_out, float* __restrict__ out) {
    int gwarp = (blockIdx.x * blockDim.x + threadIdx.x) >> 5;
    int lane  = threadIdx.x & 31;
    if (gwarp >= T_SEQ) return;
    float acc = 0.f;
#pragma unroll
    for (int i = 0; i < HID / 32; ++i)
        acc += X[(size_t)gwarp * HID + i * 32 + lane] * w_out[i * 32 + lane];
#pragma unroll
    for (int off = 16; off; off >>= 1) acc += __shfl_down_sync(0xffffffffu, acc, off);
    if (lane == 0) out[gwarp] = acc + b_out[0];
}

// ---------------- host launcher ----------------
extern "C" void kernel_launch(void* const* d_in, const int* in_sizes, int n_in,
                              void* d_out, int out_size) {
    const float* S         = (const float*)d_in[0];
    const float* h0        = (const float*)d_in[1];
    const float* w_ih0     = (const float*)d_in[2];
    const float* w_hh0     = (const float*)d_in[3];
    const float* b_ih0     = (const float*)d_in[4];
    const float* b_hh0     = (const float*)d_in[5];
    const float* w_ih_rest = (const float*)d_in[6];
    const float* w_hh_rest = (const float*)d_in[7];
    const float* b_ih_rest = (const float*)d_in[8];
    const float* b_hh_rest = (const float*)d_in[9];
    const float* w_out     = (const float*)d_in[10];
    const float* b_out     = (const float*)d_in[11];
    float* out             = (float*)d_out;

    float *gi, *Xa, *Xb;
    cudaGetSymbolAddress((void**)&gi, g_gi);
    cudaGetSymbolAddress((void**)&Xa, g_Xa);
    cudaGetSymbolAddress((void**)&Xb, g_Xb);

    dim3 ggrid(GDIM / 128, T_SEQ / 128);

    // ---- layer 0 ----
    gemm_bias_nt<<<ggrid, 256>>>(S, w_ih0, b_ih0, gi, T_SEQ, GDIM, 128);
    init_phase<<<1, 1024>>>(h0, 0);
    mgu_recur<<<NCTA, RECT>>>(w_hh0, b_hh0, gi, Xa);

    // ---- layer 1 ----
    gemm_bias_nt<<<ggrid, 256>>>(Xa, w_ih_rest, b_ih_rest, gi, T_SEQ, GDIM, HID);
    init_phase<<<1, 1024>>>(h0, 1);
    mgu_recur<<<NCTA, RECT>>>(w_hh_rest, b_hh_rest, gi, Xb);

    // ---- layer 2 ----
    gemm_bias_nt<<<ggrid, 256>>>(Xb, w_ih_rest + (size_t)GDIM * HID,
                                 b_ih_rest + GDIM, gi, T_SEQ, GDIM, HID);
    init_phase<<<1, 1024>>>(h0, 2);
    mgu_recur<<<NCTA, RECT>>>(w_hh_rest + (size_t)GDIM * HID,
                              b_hh_rest + GDIM, gi, Xa);

    // ---- output projection ----
    out_proj<<<T_SEQ * 32 / 256, 256>>>(Xa, w_out, b_out, out);
}

// round 2
// speedup vs baseline: 1.6162x; 1.6162x over previous
#include <cuda_runtime.h>
#include <math.h>

#define T_SEQ 8192
#define HID   1024
#define GDIM  2048          // 2*H
#define NCTA  128
#define RECT  256           // threads per recurrence CTA (8 warps = 8 h-outputs)

// ---------------- scratch (static __device__, no allocation) ----------------
__device__ float g_gi[T_SEQ * GDIM];     // 64 MB  input projection for current layer
__device__ float g_Xa[T_SEQ * HID];      // 32 MB  layer output ping
__device__ float g_Xb[T_SEQ * HID];      // 32 MB  layer output pong
__device__ float g_h[2][HID];            // double-buffered hidden state
__device__ int   g_arrive;               // barrier arrival counter
__device__ int   g_release;              // barrier release generation

__device__ __forceinline__ int ld_acquire_gpu(const int* p) {
    int v;
    asm volatile("ld.global.acquire.gpu.b32 %0, [%1];" : "=r"(v) : "l"(p));
    return v;
}
__device__ __forceinline__ void st_release_gpu(int* p, int v) {
    asm volatile("st.global.release.gpu.b32 [%0], %1;" :: "l"(p), "r"(v));
}

// ---------------- per-layer init: zero barrier, load h0 ----------------
__global__ void init_phase(const float* __restrict__ h0, int layer) {
    int tid = blockIdx.x * blockDim.x + threadIdx.x;
    if (tid == 0) { g_arrive = 0; g_release = 0; }
    if (tid < HID) g_h[0][tid] = h0[layer * HID + tid];
}

// ---------------- C[M,N] = A[M,K] @ W[N,K]^T + bias[N] ----------------
__global__ __launch_bounds__(256, 2)
void gemm_bias_nt(const float* __restrict__ A, const float* __restrict__ W,
                  const float* __restrict__ bias, float* __restrict__ C,
                  int M, int N, int K) {
    __shared__ float As[8][128];
    __shared__ float Bs[8][128];
    const int tid  = threadIdx.x;
    const int bm   = blockIdx.y * 128;
    const int bn   = blockIdx.x * 128;
    const int lrow = tid >> 1;           // 0..127
    const int lcol = (tid & 1) << 2;     // 0 or 4
    const int ty   = tid >> 4;           // 0..15
    const int tx   = tid & 15;           // 0..15

    float acc[8][8];
#pragma unroll
    for (int i = 0; i < 8; ++i)
#pragma unroll
        for (int j = 0; j < 8; ++j) acc[i][j] = 0.f;

    const float* Aptr = A + (size_t)(bm + lrow) * K + lcol;
    const float* Wptr = W + (size_t)(bn + lrow) * K + lcol;

    for (int k0 = 0; k0 < K; k0 += 8) {
        float4 av = *(const float4*)(Aptr + k0);
        float4 wv = *(const float4*)(Wptr + k0);
        As[lcol + 0][lrow] = av.x; As[lcol + 1][lrow] = av.y;
        As[lcol + 2][lrow] = av.z; As[lcol + 3][lrow] = av.w;
        Bs[lcol + 0][lrow] = wv.x; Bs[lcol + 1][lrow] = wv.y;
        Bs[lcol + 2][lrow] = wv.z; Bs[lcol + 3][lrow] = wv.w;
        __syncthreads();
#pragma unroll
        for (int k = 0; k < 8; ++k) {
            float4 a0 = *(const float4*)&As[k][ty * 8];
            float4 a1 = *(const float4*)&As[k][ty * 8 + 4];
            float4 b0 = *(const float4*)&Bs[k][tx * 8];
            float4 b1 = *(const float4*)&Bs[k][tx * 8 + 4];
            float ar[8] = {a0.x, a0.y, a0.z, a0.w, a1.x, a1.y, a1.z, a1.w};
            float br[8] = {b0.x, b0.y, b0.z, b0.w, b1.x, b1.y, b1.z, b1.w};
#pragma unroll
            for (int i = 0; i < 8; ++i)
#pragma unroll
                for (int j = 0; j < 8; ++j) acc[i][j] += ar[i] * br[j];
        }
        __syncthreads();
    }

#pragma unroll
    for (int i = 0; i < 8; ++i) {
        int row = bm + ty * 8 + i;
#pragma unroll
        for (int j = 0; j < 8; j += 4) {
            float4 v;
            int col = bn + tx * 8 + j;
            v.x = acc[i][j + 0] + bias[col + 0];
            v.y = acc[i][j + 1] + bias[col + 1];
            v.z = acc[i][j + 2] + bias[col + 2];
            v.w = acc[i][j + 3] + bias[col + 3];
            *(float4*)&C[(size_t)row * N + col] = v;
        }
    }
}

// ---------------- persistent MGU recurrence for one layer ----------------
// 128 CTAs x 256 threads. CTA c, warp w owns h-index j = c*8+w:
// rows j (forget) and j+1024 (candidate) of w_hh live in registers.
__global__ __launch_bounds__(RECT, 1)
void mgu_recur(const float* __restrict__ w_hh, const float* __restrict__ b_hh,
               const float* __restrict__ gi, float* __restrict__ X) {
    __shared__ float4 h_s[HID / 4];   // full h, 4 KB

    const int cta  = blockIdx.x;
    const int tid  = threadIdx.x;
    const int warp = tid >> 5;
    const int lane = tid & 31;
    const int j    = cta * 8 + warp;     // h output index / forget row
    const int rn   = j + HID;            // candidate row

    // preload this warp's two weight rows into registers (64 floats/lane)
    float4 wf[8], wn[8];
#pragma unroll
    for (int i = 0; i < 8; ++i) {
        int col = 4 * (i * 32 + lane);
        wf[i] = *(const float4*)&w_hh[(size_t)j  * HID + col];
        wn[i] = *(const float4*)&w_hh[(size_t)rn * HID + col];
    }
    const float bf  = b_hh[j];
    const float bnn = b_hh[rn];

    float x_pend = 0.f;       // deferred X store (off critical path)
    int   x_t    = -1;

    for (int t = 0; t < T_SEQ; ++t) {
        // prefetch gi for this step (independent of the barrier)
        float gif = 0.f, gin = 0.f;
        if (lane == 0) {
            gif = __ldcg(&gi[(size_t)t * GDIM + j]);
            gin = __ldcg(&gi[(size_t)t * GDIM + HID + j]);
        }

        // wait: all CTAs finished step t-1 (single-word acquire poll, 1 thread)
        if (tid == 0) {
            while (ld_acquire_gpu(&g_release) < t) {}
        }
        __syncthreads();

        // drain deferred X store from previous step (now safely ordered)
        if (lane == 0 && x_t >= 0)
            X[(size_t)x_t * HID + j] = x_pend;

        // stage h(t-1) into shared
        const float4* hsrc = (const float4*)g_h[t & 1];
        h_s[tid] = __ldcg(&hsrc[tid]);
        __syncthreads();

        // two 1024-length dot products per warp, weights in registers.
        // split accumulators to shorten the FMA dependency chains.
        float af0 = 0.f, af1 = 0.f, an0 = 0.f, an1 = 0.f;
#pragma unroll
        for (int i = 0; i < 8; i += 2) {
            float4 h4a = h_s[i * 32 + lane];
            float4 h4b = h_s[(i + 1) * 32 + lane];
            af0 += wf[i].x * h4a.x + wf[i].y * h4a.y + wf[i].z * h4a.z + wf[i].w * h4a.w;
            an0 += wn[i].x * h4a.x + wn[i].y * h4a.y + wn[i].z * h4a.z + wn[i].w * h4a.w;
            af1 += wf[i+1].x * h4b.x + wf[i+1].y * h4b.y + wf[i+1].z * h4b.z + wf[i+1].w * h4b.w;
            an1 += wn[i+1].x * h4b.x + wn[i+1].y * h4b.y + wn[i+1].z * h4b.z + wn[i+1].w * h4b.w;
        }
        float accf = af0 + af1;
        float accn = an0 + an1;
#pragma unroll
        for (int off = 16; off; off >>= 1) {
            accf += __shfl_down_sync(0xffffffffu, accf, off);
            accn += __shfl_down_sync(0xffffffffu, accn, off);
        }

        if (lane == 0) {
            float f     = 1.f / (1.f + expf(-(gif + accf + bf)));
            float n     = tanhf(gin + f * (accn + bnn));
            float hprev = ((const float*)h_s)[j];
            float hy    = n + (1.f - f) * (hprev - n);
            g_h[(t + 1) & 1][j] = hy;
            x_pend = hy;            // defer X store past the barrier publish
            x_t    = t;
        }
        __syncthreads();

        // arrive: one fence + one atomic per CTA. bar.sync + cumulative fence
        // orders all warps' g_h stores before the release.
        if (tid == 0) {
            __threadfence();
            int old = atomicAdd(&g_arrive, 1);
            if (old == t * NCTA + (NCTA - 1))
                st_release_gpu(&g_release, t + 1);
        }
    }

    // final deferred X store
    if (lane == 0 && x_t >= 0)
        X[(size_t)x_t * HID + j] = x_pend;
}

// ---------------- final projection: out[t] = X[t] . w_out + b_out ----------------
__global__ void out_proj(const float* __restrict__ X, const float* __restrict__ w_out,
                         const float* __restrict__ b_out, float* __restrict__ out) {
    int gwarp = (blockIdx.x * blockDim.x + threadIdx.x) >> 5;
    int lane  = threadIdx.x & 31;
    if (gwarp >= T_SEQ) return;
    float acc = 0.f;
#pragma unroll
    for (int i = 0; i < HID / 32; ++i)
        acc += X[(size_t)gwarp * HID + i * 32 + lane] * w_out[i * 32 + lane];
#pragma unroll
    for (int off = 16; off; off >>= 1) acc += __shfl_down_sync(0xffffffffu, acc, off);
    if (lane == 0) out[gwarp] = acc + b_out[0];
}

// ---------------- host launcher ----------------
extern "C" void kernel_launch(void* const* d_in, const int* in_sizes, int n_in,
                              void* d_out, int out_size) {
    const float* S         = (const float*)d_in[0];
    const float* h0        = (const float*)d_in[1];
    const float* w_ih0     = (const float*)d_in[2];
    const float* w_hh0     = (const float*)d_in[3];
    const float* b_ih0     = (const float*)d_in[4];
    const float* b_hh0     = (const float*)d_in[5];
    const float* w_ih_rest = (const float*)d_in[6];
    const float* w_hh_rest = (const float*)d_in[7];
    const float* b_ih_rest = (const float*)d_in[8];
    const float* b_hh_rest = (const float*)d_in[9];
    const float* w_out     = (const float*)d_in[10];
    const float* b_out     = (const float*)d_in[11];
    float* out             = (float*)d_out;

    float *gi, *Xa, *Xb;
    cudaGetSymbolAddress((void**)&gi, g_gi);
    cudaGetSymbolAddress((void**)&Xa, g_Xa);
    cudaGetSymbolAddress((void**)&Xb, g_Xb);

    dim3 ggrid(GDIM / 128, T_SEQ / 128);

    // ---- layer 0 ----
    gemm_bias_nt<<<ggrid, 256>>>(S, w_ih0, b_ih0, gi, T_SEQ, GDIM, 128);
    init_phase<<<1, 1024>>>(h0, 0);
    mgu_recur<<<NCTA, RECT>>>(w_hh0, b_hh0, gi, Xa);

    // ---- layer 1 ----
    gemm_bias_nt<<<ggrid, 256>>>(Xa, w_ih_rest, b_ih_rest, gi, T_SEQ, GDIM, HID);
    init_phase<<<1, 1024>>>(h0, 1);
    mgu_recur<<<NCTA, RECT>>>(w_hh_rest, b_hh_rest, gi, Xb);

    // ---- layer 2 ----
    gemm_bias_nt<<<ggrid, 256>>>(Xb, w_ih_rest + (size_t)GDIM * HID,
                                 b_ih_rest + GDIM, gi, T_SEQ, GDIM, HID);
    init_phase<<<1, 1024>>>(h0, 2);
    mgu_recur<<<NCTA, RECT>>>(w_hh_rest + (size_t)GDIM * HID,
                              b_hh_rest + GDIM, gi, Xa);

    // ---- output projection ----
    out_proj<<<T_SEQ * 32 / 256, 256>>>(Xa, w_out, b_out, out);
}